// round 13
// baseline (speedup 1.0000x reference)
#include <cuda_runtime.h>
#include <mma.h>
#include <cstdint>

using namespace nvcuda;

#define T_STEPS 1024
#define B_SZ    64
#define H_SZ    1024
#define BH      (B_SZ * H_SZ)          /* 65536 */
#define TBH     (T_STEPS * BH)

// ---------------- config ----------------
#define RSZ   16         // batch rows per block
#define CSZ   32         // output cols per block
#define NBLK  128        // 4 row-groups x 32 col-blocks
#define KCH   64         // k columns per warp chunk
#define NWARP 16
#define SST   36         // stage row stride (floats)
#define FPAD  32         // one flag per 128B L2 line
#define RING  4          // xs-swizzle ring depth

__device__ unsigned g_flags[NBLK * FPAD];
__device__ __align__(16) float g_hswz[2][BH];        // fragment-major h ping-pong
__device__ __align__(16) float g_xswz[RING][BH];     // fragment-major xs ring (1MB)

// ---------------- asm helpers ----------------
__device__ __forceinline__ unsigned ldacq(const unsigned* p) {
    unsigned v;
    asm volatile("ld.acquire.gpu.global.u32 %0, [%1];" : "=r"(v) : "l"(p));
    return v;
}
__device__ __forceinline__ unsigned ldflag(const unsigned* p) {
    unsigned v;
    asm volatile("ld.global.cg.u32 %0, [%1];" : "=r"(v) : "l"(p));
    return v;
}
__device__ __forceinline__ void relexch(unsigned* p, unsigned v) {
    unsigned old;
    asm volatile("atom.release.gpu.global.exch.b32 %0, [%1], %2;"
                 : "=r"(old) : "l"(p), "r"(v) : "memory");
}
__device__ __forceinline__ void mma_tf32(float acc[4], const uint4& a, const uint2& b) {
    asm volatile("mma.sync.aligned.m16n8k8.row.col.f32.tf32.tf32.f32 "
                 "{%0,%1,%2,%3}, {%4,%5,%6,%7}, {%8,%9}, {%0,%1,%2,%3};"
                 : "+f"(acc[0]), "+f"(acc[1]), "+f"(acc[2]), "+f"(acc[3])
                 : "r"(a.x), "r"(a.y), "r"(a.z), "r"(a.w), "r"(b.x), "r"(b.y));
}

// fragment-major offset (within one rb slice) for element (r16, gc)
__device__ __forceinline__ int swz_rel(int r16, int gc) {
    int reg  = ((r16 >= 8) ? 1 : 0) | ((gc & 4) ? 2 : 0);
    int lane = 4 * (r16 & 7) + (gc & 3);
    return (((gc >> 6) * 8 + ((gc >> 3) & 7)) * 32 + lane) * 4 + reg;
}

// ---------------------------------------------------------------------------
// Fused persistent kernel, PAIRED steps: one pass over Wih fragments feeds
// xproj MMAs for steps t AND t+1 (acc for t+1 held in registers across the
// pair) — halves the dominant Wih LDS traffic. Guards: phase-A poll flag>=t
// covers ring slots t (written t-2) and t+1 (written t-1); duty writes
// slots t+2/t+3 after that poll; ring slots used in a pair are disjoint mod 4.
// ---------------------------------------------------------------------------
__global__ void __launch_bounds__(512) rnn_fused(const float* __restrict__ init,
                                                 const float* __restrict__ xs,
                                                 const float* __restrict__ Wih,
                                                 const float* __restrict__ bih,
                                                 const float* __restrict__ Whh,
                                                 const float* __restrict__ bhh,
                                                 float* __restrict__ outs,
                                                 float* __restrict__ carry) {
    extern __shared__ float sm[];
    uint2* WihF  = reinterpret_cast<uint2*>(sm);     // 16*8*4*32 uint2 = 131072 B
    float* stage = sm + 2 * (NWARP * 8 * 4 * 32);    // 16*16*36 f = 36864 B

    const int tid = threadIdx.x, bid = blockIdx.x;
    const int rb = bid & 3, jb = bid >> 2;
    const int r0 = rb * RSZ, j0 = jb * CSZ;
    const int w = tid >> 5, lane = tid & 31;
    const int g = lane >> 2, tg = lane & 3;
    const int c = (w + jb) & 15;             // staggered chunk
    const int er = w, ec = lane;             // this thread's output element

    unsigned* myflag = &g_flags[bid * FPAD];
    const unsigned base = ldflag(myflag);
    const float bsum = bih[j0 + ec] + bhh[j0 + ec];

    const int myswz = swz_rel(er, j0 + ec);
    const int rbbase = rb * 16384;
    const size_t eoff = (size_t)(r0 + er) * H_SZ + j0 + ec;

    // producer flags for chunk c: blocks (rb, 2c) and (rb, 2c+1)
    const unsigned* pflag =
        &g_flags[((((unsigned)(2 * c + (lane & 1))) << 2) | (unsigned)rb) * FPAD];

    // ---- prologue: Wih fragments -> smem, fragment-major (warp w fills chunk c)
#pragma unroll
    for (int kk = 0; kk < 8; kk++)
#pragma unroll
        for (int nt = 0; nt < 4; nt++) {
            int krow = c * KCH + kk * 8 + tg;
            int ncol = j0 + nt * 8 + g;
            uint2 v;
            v.x = __float_as_uint(wmma::__float_to_tf32(Wih[(size_t)krow * H_SZ + ncol]));
            v.y = __float_as_uint(wmma::__float_to_tf32(Wih[(size_t)(krow + 4) * H_SZ + ncol]));
            WihF[((c * 8 + kk) * 4 + nt) * 32 + lane] = v;
        }

    // ---- prologue: Whh fragments -> registers (64 regs) ----
    uint2 Bf[8][4];
#pragma unroll
    for (int kk = 0; kk < 8; kk++)
#pragma unroll
        for (int nt = 0; nt < 4; nt++) {
            int krow = c * KCH + kk * 8 + tg;
            int ncol = j0 + nt * 8 + g;
            Bf[kk][nt].x = __float_as_uint(
                wmma::__float_to_tf32(Whh[(size_t)krow * H_SZ + ncol]));
            Bf[kk][nt].y = __float_as_uint(
                wmma::__float_to_tf32(Whh[(size_t)(krow + 4) * H_SZ + ncol]));
        }

    // ---- prologue: duplicate-swizzle init -> hswz[1], xs[0]->ring0, xs[1]->ring1
#pragma unroll 4
    for (int i = 0; i < 32; i++) {
        int idx = tid + i * 512;             // 0..16383
        int r16 = idx >> 10, gc = idx & 1023;
        int off = rbbase + swz_rel(r16, gc);
        size_t src = (size_t)(r0 + r16) * H_SZ + gc;
        g_hswz[1][off]  = wmma::__float_to_tf32(init[src]);
        g_xswz[0][off]  = wmma::__float_to_tf32(__ldcg(xs + src));
        g_xswz[1][off]  = wmma::__float_to_tf32(__ldcg(xs + BH + src));
    }
    __syncthreads();

#pragma unroll 1
    for (int t = 0; t < T_STEPS; t += 2) {
        // canonical xs reads for swizzle duty (steps t+2, t+3), issued early
        float xv2 = 0.0f, xv3 = 0.0f;
        if (t + 2 < T_STEPS) xv2 = __ldcg(xs + (size_t)(t + 2) * BH + eoff);
        if (t + 3 < T_STEPS) xv3 = __ldcg(xs + (size_t)(t + 3) * BH + eoff);

        // ===== phase A guard: h[t-1] ready; also certifies ring slots t, t+1
        if (t > 0) {
            for (;;) {
                int ok = (lane < 2) ? ((int)(ldacq(pflag) - base) >= t) : 1;
                if (__all_sync(0xffffffffu, ok)) break;
                __nanosleep(16);
            }
        }

        float accC[4][4] = {{0,0,0,0},{0,0,0,0},{0,0,0,0},{0,0,0,0}};
        float accN[4][4] = {{0,0,0,0},{0,0,0,0},{0,0,0,0},{0,0,0,0}};

        // paired xproj MMAs: ONE Wih fetch feeds steps t and t+1
        {
            const uint4* ap0 = reinterpret_cast<const uint4*>(
                g_xswz[t & (RING - 1)] + rbbase + (c * 8) * 128) + lane;
            const uint4* ap1 = reinterpret_cast<const uint4*>(
                g_xswz[(t + 1) & (RING - 1)] + rbbase + (c * 8) * 128) + lane;
            const uint2* wp = WihF + (c * 8) * 4 * 32 + lane;
#pragma unroll
            for (int kk = 0; kk < 8; kk++) {
                uint4 a0 = __ldcg(ap0 + kk * 32);
                uint4 a1 = __ldcg(ap1 + kk * 32);
#pragma unroll
                for (int nt = 0; nt < 4; nt++) {
                    uint2 wf = wp[(kk * 4 + nt) * 32];
                    mma_tf32(accC[nt], a0, wf);
                    mma_tf32(accN[nt], a1, wf);
                }
            }
        }

        // swizzle duty: publish xs[t+2], xs[t+3] (slots free, readers certified)
        if (t + 2 < T_STEPS)
            __stcg(&g_xswz[(t + 2) & (RING - 1)][rbbase + myswz],
                   wmma::__float_to_tf32(xv2));
        if (t + 3 < T_STEPS)
            __stcg(&g_xswz[(t + 3) & (RING - 1)][rbbase + myswz],
                   wmma::__float_to_tf32(xv3));

        // recurrent MMAs step t: A from h ping-pong, B = Whh registers
        {
            const uint4* ap = reinterpret_cast<const uint4*>(
                g_hswz[(t + 1) & 1] + rbbase + (c * 8) * 128) + lane;
            uint4 av = __ldcg(ap);
#pragma unroll
            for (int kk = 0; kk < 8; kk++) {
                uint4 nx;
                if (kk < 7) nx = __ldcg(ap + (kk + 1) * 32);
#pragma unroll
                for (int nt = 0; nt < 4; nt++)
                    mma_tf32(accC[nt], av, Bf[kk][nt]);
                av = nx;
            }
        }

        // stage + reduce + publish step t
        float* stg = stage + w * (RSZ * SST);
#pragma unroll
        for (int nt = 0; nt < 4; nt++) {
            *reinterpret_cast<float2*>(stg + g * SST + nt * 8 + 2 * tg) =
                make_float2(accC[nt][0], accC[nt][1]);
            *reinterpret_cast<float2*>(stg + (g + 8) * SST + nt * 8 + 2 * tg) =
                make_float2(accC[nt][2], accC[nt][3]);
        }
        __syncthreads();

        float v = bsum;
#pragma unroll
        for (int k = 0; k < NWARP; k++)
            v += stage[k * (RSZ * SST) + er * SST + ec];
        v = wmma::__float_to_tf32(tanhf(v));

        __stcg(&g_hswz[t & 1][rbbase + myswz], v);
        __syncthreads();
        if (tid == 0) relexch(myflag, base + (unsigned)(t + 1));
        __stcg(outs + (size_t)t * BH + eoff, v);

        // ===== phase B: step t+1 =====
        for (;;) {
            int ok = (lane < 2) ? ((int)(ldacq(pflag) - base) >= t + 1) : 1;
            if (__all_sync(0xffffffffu, ok)) break;
            __nanosleep(16);
        }

        {
            const uint4* ap = reinterpret_cast<const uint4*>(
                g_hswz[t & 1] + rbbase + (c * 8) * 128) + lane;
            uint4 av = __ldcg(ap);
#pragma unroll
            for (int kk = 0; kk < 8; kk++) {
                uint4 nx;
                if (kk < 7) nx = __ldcg(ap + (kk + 1) * 32);
#pragma unroll
                for (int nt = 0; nt < 4; nt++)
                    mma_tf32(accN[nt], av, Bf[kk][nt]);
                av = nx;
            }
        }

#pragma unroll
        for (int nt = 0; nt < 4; nt++) {
            *reinterpret_cast<float2*>(stg + g * SST + nt * 8 + 2 * tg) =
                make_float2(accN[nt][0], accN[nt][1]);
            *reinterpret_cast<float2*>(stg + (g + 8) * SST + nt * 8 + 2 * tg) =
                make_float2(accN[nt][2], accN[nt][3]);
        }
        __syncthreads();

        v = bsum;
#pragma unroll
        for (int k = 0; k < NWARP; k++)
            v += stage[k * (RSZ * SST) + er * SST + ec];
        v = wmma::__float_to_tf32(tanhf(v));

        __stcg(&g_hswz[(t + 1) & 1][rbbase + myswz], v);
        __syncthreads();
        if (tid == 0) relexch(myflag, base + (unsigned)(t + 2));
        __stcg(outs + (size_t)(t + 1) * BH + eoff, v);
        if (carry != nullptr && t + 1 == T_STEPS - 1)
            __stcg(carry + eoff, v);
    }
}

// ---------------------------------------------------------------------------
extern "C" void kernel_launch(void* const* d_in, const int* in_sizes, int n_in,
                              void* d_out, int out_size) {
    const float* init = (const float*)d_in[0];
    const float* xs   = (const float*)d_in[1];
    const float* Wih  = (const float*)d_in[2];
    const float* bih  = (const float*)d_in[3];
    const float* Whh  = (const float*)d_in[4];
    const float* bhh  = (const float*)d_in[5];

    float* out   = (float*)d_out;
    float* carry = nullptr;
    float* outs;
    if (out_size == BH + TBH) { carry = out; outs = out + BH; }
    else                      { outs = out; }

    int smem = (NWARP * 8 * 4 * 32 * 2 + NWARP * RSZ * SST) * (int)sizeof(float); // 167936B
    cudaFuncSetAttribute(rnn_fused, cudaFuncAttributeMaxDynamicSharedMemorySize, smem);
    rnn_fused<<<NBLK, 512, smem>>>(init, xs, Wih, bih, Whh, bhh, outs, carry);
}

// round 14
// speedup vs baseline: 1.4332x; 1.4332x over previous
#include <cuda_runtime.h>
#include <mma.h>
#include <cstdint>

using namespace nvcuda;

#define T_STEPS 1024
#define B_SZ    64
#define H_SZ    1024
#define BH      (B_SZ * H_SZ)          /* 65536 */
#define TBH     (T_STEPS * BH)

// ---------------- config ----------------
#define RSZ   16         // batch rows per block
#define CSZ   32         // output cols per block
#define NBLK  128        // 4 row-groups x 32 col-blocks
#define KCH   64         // k columns per warp chunk
#define NWARP 16
#define SST   36         // stage row stride (floats)
#define FPAD  32         // one flag per 128B L2 line
#define RING  4          // xs-swizzle ring depth

__device__ unsigned g_flags[NBLK * FPAD];
__device__ __align__(16) float g_hswz[2][BH];        // fragment-major h ping-pong
__device__ __align__(16) float g_xswz[RING][BH];     // fragment-major xs ring (1MB)

// ---------------- asm helpers ----------------
__device__ __forceinline__ unsigned ldacq(const unsigned* p) {
    unsigned v;
    asm volatile("ld.acquire.gpu.global.u32 %0, [%1];" : "=r"(v) : "l"(p));
    return v;
}
__device__ __forceinline__ unsigned ldflag(const unsigned* p) {
    unsigned v;
    asm volatile("ld.global.cg.u32 %0, [%1];" : "=r"(v) : "l"(p));
    return v;
}
__device__ __forceinline__ void relexch(unsigned* p, unsigned v) {
    unsigned old;
    asm volatile("atom.release.gpu.global.exch.b32 %0, [%1], %2;"
                 : "=r"(old) : "l"(p), "r"(v) : "memory");
}
__device__ __forceinline__ void mma_tf32(float acc[4], const uint4& a, const uint2& b) {
    asm volatile("mma.sync.aligned.m16n8k8.row.col.f32.tf32.tf32.f32 "
                 "{%0,%1,%2,%3}, {%4,%5,%6,%7}, {%8,%9}, {%0,%1,%2,%3};"
                 : "+f"(acc[0]), "+f"(acc[1]), "+f"(acc[2]), "+f"(acc[3])
                 : "r"(a.x), "r"(a.y), "r"(a.z), "r"(a.w), "r"(b.x), "r"(b.y));
}

// fragment-major offset (within one rb slice) for element (r16, gc)
__device__ __forceinline__ int swz_rel(int r16, int gc) {
    int reg  = ((r16 >= 8) ? 1 : 0) | ((gc & 4) ? 2 : 0);
    int lane = 4 * (r16 & 7) + (gc & 3);
    return (((gc >> 6) * 8 + ((gc >> 3) & 7)) * 32 + lane) * 4 + reg;
}

// ---------------------------------------------------------------------------
// Fused persistent kernel (round-12 structure, proven 2844us) plus:
//  - speculative flag pre-read at step top: if peers already published,
//    the post-xproj poll (a dependent L2 round trip) is skipped entirely
//  - spin-first-then-sleep poll to cut nanosleep wakeup quantization
// ---------------------------------------------------------------------------
__global__ void __launch_bounds__(512) rnn_fused(const float* __restrict__ init,
                                                 const float* __restrict__ xs,
                                                 const float* __restrict__ Wih,
                                                 const float* __restrict__ bih,
                                                 const float* __restrict__ Whh,
                                                 const float* __restrict__ bhh,
                                                 float* __restrict__ outs,
                                                 float* __restrict__ carry) {
    extern __shared__ float sm[];
    uint2* WihF  = reinterpret_cast<uint2*>(sm);     // 16*8*4*32 uint2 = 131072 B
    float* stage = sm + 2 * (NWARP * 8 * 4 * 32);    // 16*16*36 f = 36864 B

    const int tid = threadIdx.x, bid = blockIdx.x;
    const int rb = bid & 3, jb = bid >> 2;
    const int r0 = rb * RSZ, j0 = jb * CSZ;
    const int w = tid >> 5, lane = tid & 31;
    const int g = lane >> 2, tg = lane & 3;
    const int c = (w + jb) & 15;             // staggered chunk
    const int er = w, ec = lane;             // this thread's output element

    unsigned* myflag = &g_flags[bid * FPAD];
    const unsigned base = ldflag(myflag);
    const float bsum = bih[j0 + ec] + bhh[j0 + ec];

    const int myswz = swz_rel(er, j0 + ec);
    const int rbbase = rb * 16384;
    const size_t eoff = (size_t)(r0 + er) * H_SZ + j0 + ec;

    // producer flags for chunk c: blocks (rb, 2c) and (rb, 2c+1)
    const unsigned* pflag =
        &g_flags[((((unsigned)(2 * c + (lane & 1))) << 2) | (unsigned)rb) * FPAD];

    // ---- prologue: Wih fragments -> smem, fragment-major (warp w fills chunk c)
#pragma unroll
    for (int kk = 0; kk < 8; kk++)
#pragma unroll
        for (int nt = 0; nt < 4; nt++) {
            int krow = c * KCH + kk * 8 + tg;
            int ncol = j0 + nt * 8 + g;
            uint2 v;
            v.x = __float_as_uint(wmma::__float_to_tf32(Wih[(size_t)krow * H_SZ + ncol]));
            v.y = __float_as_uint(wmma::__float_to_tf32(Wih[(size_t)(krow + 4) * H_SZ + ncol]));
            WihF[((c * 8 + kk) * 4 + nt) * 32 + lane] = v;
        }

    // ---- prologue: Whh fragments -> registers (64 regs) ----
    uint2 Bf[8][4];
#pragma unroll
    for (int kk = 0; kk < 8; kk++)
#pragma unroll
        for (int nt = 0; nt < 4; nt++) {
            int krow = c * KCH + kk * 8 + tg;
            int ncol = j0 + nt * 8 + g;
            Bf[kk][nt].x = __float_as_uint(
                wmma::__float_to_tf32(Whh[(size_t)krow * H_SZ + ncol]));
            Bf[kk][nt].y = __float_as_uint(
                wmma::__float_to_tf32(Whh[(size_t)(krow + 4) * H_SZ + ncol]));
        }

    // ---- prologue: duplicate-swizzle init -> hswz[1], xs[0]->ring0, xs[1]->ring1
#pragma unroll 4
    for (int i = 0; i < 32; i++) {
        int idx = tid + i * 512;             // 0..16383
        int r16 = idx >> 10, gc = idx & 1023;
        int off = rbbase + swz_rel(r16, gc);
        size_t src = (size_t)(r0 + r16) * H_SZ + gc;
        g_hswz[1][off]  = wmma::__float_to_tf32(init[src]);
        g_xswz[0][off]  = wmma::__float_to_tf32(__ldcg(xs + src));
        g_xswz[1][off]  = wmma::__float_to_tf32(__ldcg(xs + BH + src));
    }
    __syncthreads();

#pragma unroll 1
    for (int t = 0; t < T_STEPS; t++) {
        // speculative flag pre-read (acquire) — often already >= t in steady state
        unsigned fspec = 0;
        if (t > 0 && lane < 2) fspec = ldacq(pflag);

        // canonical xs read for swizzle duty (step t+2), DRAM, issued early
        float xval = 0.0f;
        if (t + 2 < T_STEPS)
            xval = __ldcg(xs + (size_t)(t + 2) * BH + eoff);

        // xproj MMAs immediately — xs ring slot t guarded by h-poll at step t-1
        float acc[4][4] = {{0,0,0,0},{0,0,0,0},{0,0,0,0},{0,0,0,0}};
        {
            const uint4* ap = reinterpret_cast<const uint4*>(
                g_xswz[t & (RING - 1)] + rbbase + (c * 8) * 128) + lane;
            const uint2* wp = WihF + (c * 8) * 4 * 32 + lane;
            uint4 av = __ldcg(ap);
#pragma unroll
            for (int kk = 0; kk < 8; kk++) {
                uint4 nx;
                if (kk < 7) nx = __ldcg(ap + (kk + 1) * 32);
#pragma unroll
                for (int nt = 0; nt < 4; nt++)
                    mma_tf32(acc[nt], av, wp[(kk * 4 + nt) * 32]);
                av = nx;
            }
        }

        // swizzle duty: publish xs[t+2] share into ring
        if (t + 2 < T_STEPS)
            __stcg(&g_xswz[(t + 2) & (RING - 1)][rbbase + myswz],
                   wmma::__float_to_tf32(xval));

        // h guard: skip poll if speculative read already satisfied
        if (t > 0) {
            int ok = (lane < 2) ? ((int)(fspec - base) >= t) : 1;
            if (!__all_sync(0xffffffffu, ok)) {
                int spin = 0;
                for (;;) {
                    ok = (lane < 2) ? ((int)(ldacq(pflag) - base) >= t) : 1;
                    if (__all_sync(0xffffffffu, ok)) break;
                    if (++spin > 48) __nanosleep(20);
                }
            }
        }

        // recurrent MMAs: A from h ping-pong (L2), B = Whh registers
        {
            const uint4* ap = reinterpret_cast<const uint4*>(
                g_hswz[(t + 1) & 1] + rbbase + (c * 8) * 128) + lane;
            uint4 av = __ldcg(ap);
#pragma unroll
            for (int kk = 0; kk < 8; kk++) {
                uint4 nx;
                if (kk < 7) nx = __ldcg(ap + (kk + 1) * 32);
#pragma unroll
                for (int nt = 0; nt < 4; nt++)
                    mma_tf32(acc[nt], av, Bf[kk][nt]);
                av = nx;
            }
        }

        // stage partials
        float* stg = stage + w * (RSZ * SST);
#pragma unroll
        for (int nt = 0; nt < 4; nt++) {
            *reinterpret_cast<float2*>(stg + g * SST + nt * 8 + 2 * tg) =
                make_float2(acc[nt][0], acc[nt][1]);
            *reinterpret_cast<float2*>(stg + (g + 8) * SST + nt * 8 + 2 * tg) =
                make_float2(acc[nt][2], acc[nt][3]);
        }
        __syncthreads();

        // epilogue: reduce 16 partials (xproj + recurrent fused), tanh
        float v = bsum;
#pragma unroll
        for (int k = 0; k < NWARP; k++)
            v += stage[k * (RSZ * SST) + er * SST + ec];
        v = wmma::__float_to_tf32(tanhf(v));

        // publish h (L2 ping-pong) FIRST, then barrier + release; DRAM after
        __stcg(&g_hswz[t & 1][rbbase + myswz], v);
        __syncthreads();
        if (tid == 0) relexch(myflag, base + (unsigned)(t + 1));

        __stcg(outs + (size_t)t * BH + eoff, v);
        if (carry != nullptr && t == T_STEPS - 1)
            __stcg(carry + eoff, v);
    }
}

// ---------------------------------------------------------------------------
extern "C" void kernel_launch(void* const* d_in, const int* in_sizes, int n_in,
                              void* d_out, int out_size) {
    const float* init = (const float*)d_in[0];
    const float* xs   = (const float*)d_in[1];
    const float* Wih  = (const float*)d_in[2];
    const float* bih  = (const float*)d_in[3];
    const float* Whh  = (const float*)d_in[4];
    const float* bhh  = (const float*)d_in[5];

    float* out   = (float*)d_out;
    float* carry = nullptr;
    float* outs;
    if (out_size == BH + TBH) { carry = out; outs = out + BH; }
    else                      { outs = out; }

    int smem = (NWARP * 8 * 4 * 32 * 2 + NWARP * RSZ * SST) * (int)sizeof(float); // 167936B
    cudaFuncSetAttribute(rnn_fused, cudaFuncAttributeMaxDynamicSharedMemorySize, smem);
    rnn_fused<<<NBLK, 512, smem>>>(init, xs, Wih, bih, Whh, bhh, outs, carry);
}

// round 15
// speedup vs baseline: 1.5395x; 1.0742x over previous
#include <cuda_runtime.h>
#include <mma.h>
#include <cstdint>

using namespace nvcuda;

#define T_STEPS 1024
#define B_SZ    64
#define H_SZ    1024
#define BH      (B_SZ * H_SZ)          /* 65536 */
#define TBH     (T_STEPS * BH)

// ---------------- config ----------------
#define RSZ   16         // batch rows per block
#define CSZ   32         // output cols per block
#define NBLK  128        // 4 row-groups x 32 col-blocks
#define KCH   64         // k columns per warp chunk
#define NWARP 16
#define SST   36         // stage row stride (floats)
#define FPAD  32         // one flag per 128B L2 line
#define RING  4          // xs-swizzle ring depth

__device__ unsigned g_flags[NBLK * FPAD];
__device__ __align__(16) float g_hswz[2][BH];        // fragment-major h ping-pong
__device__ __align__(16) float g_xswz[RING][BH];     // fragment-major xs ring (1MB)

// ---------------- asm helpers ----------------
__device__ __forceinline__ unsigned ldacq(const unsigned* p) {
    unsigned v;
    asm volatile("ld.acquire.gpu.global.u32 %0, [%1];" : "=r"(v) : "l"(p));
    return v;
}
__device__ __forceinline__ unsigned ldflag(const unsigned* p) {
    unsigned v;
    asm volatile("ld.global.cg.u32 %0, [%1];" : "=r"(v) : "l"(p));
    return v;
}
__device__ __forceinline__ void relexch(unsigned* p, unsigned v) {
    unsigned old;
    asm volatile("atom.release.gpu.global.exch.b32 %0, [%1], %2;"
                 : "=r"(old) : "l"(p), "r"(v) : "memory");
}
__device__ __forceinline__ void mma_tf32(float acc[4], const uint4& a, const uint2& b) {
    asm volatile("mma.sync.aligned.m16n8k8.row.col.f32.tf32.tf32.f32 "
                 "{%0,%1,%2,%3}, {%4,%5,%6,%7}, {%8,%9}, {%0,%1,%2,%3};"
                 : "+f"(acc[0]), "+f"(acc[1]), "+f"(acc[2]), "+f"(acc[3])
                 : "r"(a.x), "r"(a.y), "r"(a.z), "r"(a.w), "r"(b.x), "r"(b.y));
}

// fragment-major offset (within one rb slice) for element (r16, gc)
__device__ __forceinline__ int swz_rel(int r16, int gc) {
    int reg  = ((r16 >= 8) ? 1 : 0) | ((gc & 4) ? 2 : 0);
    int lane = 4 * (r16 & 7) + (gc & 3);
    return (((gc >> 6) * 8 + ((gc >> 3) & 7)) * 32 + lane) * 4 + reg;
}

// ---------------------------------------------------------------------------
// Fused persistent kernel (round-12 structure, proven 2844us) with ONE delta:
// A-fragment loads in BOTH GEMM phases run through a 4-deep register ring
// (MLP=4 instead of 2) — halves the exposed L2 latency per phase; the
// recurrent phase sits on the serial chain, so this cuts the step cadence.
// ---------------------------------------------------------------------------
__global__ void __launch_bounds__(512) rnn_fused(const float* __restrict__ init,
                                                 const float* __restrict__ xs,
                                                 const float* __restrict__ Wih,
                                                 const float* __restrict__ bih,
                                                 const float* __restrict__ Whh,
                                                 const float* __restrict__ bhh,
                                                 float* __restrict__ outs,
                                                 float* __restrict__ carry) {
    extern __shared__ float sm[];
    uint2* WihF  = reinterpret_cast<uint2*>(sm);     // 16*8*4*32 uint2 = 131072 B
    float* stage = sm + 2 * (NWARP * 8 * 4 * 32);    // 16*16*36 f = 36864 B

    const int tid = threadIdx.x, bid = blockIdx.x;
    const int rb = bid & 3, jb = bid >> 2;
    const int r0 = rb * RSZ, j0 = jb * CSZ;
    const int w = tid >> 5, lane = tid & 31;
    const int g = lane >> 2, tg = lane & 3;
    const int c = (w + jb) & 15;             // staggered chunk
    const int er = w, ec = lane;             // this thread's output element

    unsigned* myflag = &g_flags[bid * FPAD];
    const unsigned base = ldflag(myflag);
    const float bsum = bih[j0 + ec] + bhh[j0 + ec];

    const int myswz = swz_rel(er, j0 + ec);
    const int rbbase = rb * 16384;
    const size_t eoff = (size_t)(r0 + er) * H_SZ + j0 + ec;

    // producer flags for chunk c: blocks (rb, 2c) and (rb, 2c+1)
    const unsigned* pflag =
        &g_flags[((((unsigned)(2 * c + (lane & 1))) << 2) | (unsigned)rb) * FPAD];

    // ---- prologue: Wih fragments -> smem, fragment-major (warp w fills chunk c)
#pragma unroll
    for (int kk = 0; kk < 8; kk++)
#pragma unroll
        for (int nt = 0; nt < 4; nt++) {
            int krow = c * KCH + kk * 8 + tg;
            int ncol = j0 + nt * 8 + g;
            uint2 v;
            v.x = __float_as_uint(wmma::__float_to_tf32(Wih[(size_t)krow * H_SZ + ncol]));
            v.y = __float_as_uint(wmma::__float_to_tf32(Wih[(size_t)(krow + 4) * H_SZ + ncol]));
            WihF[((c * 8 + kk) * 4 + nt) * 32 + lane] = v;
        }

    // ---- prologue: Whh fragments -> registers (64 regs) ----
    uint2 Bf[8][4];
#pragma unroll
    for (int kk = 0; kk < 8; kk++)
#pragma unroll
        for (int nt = 0; nt < 4; nt++) {
            int krow = c * KCH + kk * 8 + tg;
            int ncol = j0 + nt * 8 + g;
            Bf[kk][nt].x = __float_as_uint(
                wmma::__float_to_tf32(Whh[(size_t)krow * H_SZ + ncol]));
            Bf[kk][nt].y = __float_as_uint(
                wmma::__float_to_tf32(Whh[(size_t)(krow + 4) * H_SZ + ncol]));
        }

    // ---- prologue: duplicate-swizzle init -> hswz[1], xs[0]->ring0, xs[1]->ring1
#pragma unroll 4
    for (int i = 0; i < 32; i++) {
        int idx = tid + i * 512;             // 0..16383
        int r16 = idx >> 10, gc = idx & 1023;
        int off = rbbase + swz_rel(r16, gc);
        size_t src = (size_t)(r0 + r16) * H_SZ + gc;
        g_hswz[1][off]  = wmma::__float_to_tf32(init[src]);
        g_xswz[0][off]  = wmma::__float_to_tf32(__ldcg(xs + src));
        g_xswz[1][off]  = wmma::__float_to_tf32(__ldcg(xs + BH + src));
    }
    __syncthreads();

#pragma unroll 1
    for (int t = 0; t < T_STEPS; t++) {
        // canonical xs read for swizzle duty (step t+2), DRAM, issued early
        float xval = 0.0f;
        if (t + 2 < T_STEPS)
            xval = __ldcg(xs + (size_t)(t + 2) * BH + eoff);

        // xproj MMAs — xs ring slot t guarded by h-poll at step t-1; MLP-4 loads
        float acc[4][4] = {{0,0,0,0},{0,0,0,0},{0,0,0,0},{0,0,0,0}};
        {
            const uint4* ap = reinterpret_cast<const uint4*>(
                g_xswz[t & (RING - 1)] + rbbase + (c * 8) * 128) + lane;
            const uint2* wp = WihF + (c * 8) * 4 * 32 + lane;
            uint4 abuf[4];
#pragma unroll
            for (int i = 0; i < 4; i++) abuf[i] = __ldcg(ap + i * 32);
#pragma unroll
            for (int kk = 0; kk < 8; kk++) {
                uint4 av = abuf[kk & 3];
                if (kk + 4 < 8) abuf[kk & 3] = __ldcg(ap + (kk + 4) * 32);
#pragma unroll
                for (int nt = 0; nt < 4; nt++)
                    mma_tf32(acc[nt], av, wp[(kk * 4 + nt) * 32]);
            }
        }

        // swizzle duty: publish xs[t+2] share into ring
        if (t + 2 < T_STEPS)
            __stcg(&g_xswz[(t + 2) & (RING - 1)][rbbase + myswz],
                   wmma::__float_to_tf32(xval));

        // h guard: acquire-poll (single trip per detection)
        if (t > 0) {
            for (;;) {
                int ok = (lane < 2) ? ((int)(ldacq(pflag) - base) >= t) : 1;
                if (__all_sync(0xffffffffu, ok)) break;
                __nanosleep(16);
            }
        }

        // recurrent MMAs: A from h ping-pong (L2), B = Whh registers; MLP-4 loads
        {
            const uint4* ap = reinterpret_cast<const uint4*>(
                g_hswz[(t + 1) & 1] + rbbase + (c * 8) * 128) + lane;
            uint4 abuf[4];
#pragma unroll
            for (int i = 0; i < 4; i++) abuf[i] = __ldcg(ap + i * 32);
#pragma unroll
            for (int kk = 0; kk < 8; kk++) {
                uint4 av = abuf[kk & 3];
                if (kk + 4 < 8) abuf[kk & 3] = __ldcg(ap + (kk + 4) * 32);
#pragma unroll
                for (int nt = 0; nt < 4; nt++)
                    mma_tf32(acc[nt], av, Bf[kk][nt]);
            }
        }

        // stage partials
        float* stg = stage + w * (RSZ * SST);
#pragma unroll
        for (int nt = 0; nt < 4; nt++) {
            *reinterpret_cast<float2*>(stg + g * SST + nt * 8 + 2 * tg) =
                make_float2(acc[nt][0], acc[nt][1]);
            *reinterpret_cast<float2*>(stg + (g + 8) * SST + nt * 8 + 2 * tg) =
                make_float2(acc[nt][2], acc[nt][3]);
        }
        __syncthreads();

        // epilogue: reduce 16 partials (xproj + recurrent fused), tanh
        float v = bsum;
#pragma unroll
        for (int k = 0; k < NWARP; k++)
            v += stage[k * (RSZ * SST) + er * SST + ec];
        v = wmma::__float_to_tf32(tanhf(v));

        // publish h (L2 ping-pong) FIRST, then barrier + release; DRAM after
        __stcg(&g_hswz[t & 1][rbbase + myswz], v);
        __syncthreads();
        if (tid == 0) relexch(myflag, base + (unsigned)(t + 1));

        __stcg(outs + (size_t)t * BH + eoff, v);
        if (carry != nullptr && t == T_STEPS - 1)
            __stcg(carry + eoff, v);
    }
}

// ---------------------------------------------------------------------------
extern "C" void kernel_launch(void* const* d_in, const int* in_sizes, int n_in,
                              void* d_out, int out_size) {
    const float* init = (const float*)d_in[0];
    const float* xs   = (const float*)d_in[1];
    const float* Wih  = (const float*)d_in[2];
    const float* bih  = (const float*)d_in[3];
    const float* Whh  = (const float*)d_in[4];
    const float* bhh  = (const float*)d_in[5];

    float* out   = (float*)d_out;
    float* carry = nullptr;
    float* outs;
    if (out_size == BH + TBH) { carry = out; outs = out + BH; }
    else                      { outs = out; }

    int smem = (NWARP * 8 * 4 * 32 * 2 + NWARP * RSZ * SST) * (int)sizeof(float); // 167936B
    cudaFuncSetAttribute(rnn_fused, cudaFuncAttributeMaxDynamicSharedMemorySize, smem);
    rnn_fused<<<NBLK, 512, smem>>>(init, xs, Wih, bih, Whh, bhh, outs, carry);
}